// round 15
// baseline (speedup 1.0000x reference)
#include <cuda_runtime.h>
#include <cuda_fp16.h>
#include <cstdint>

// NearestEmbed (VQ): fp16 hh MMA screen (rigorous margin) + candidate rescue:
// flagged points re-scan hh-only; codes with d~ < stored threshold get exact
// fp32 re-score from a transposed codebook. 3x less rescue MMA work than R14.
// x [32,64,64,64] f32, emb [64,1024] f32
// out = [ result (8388608 f32) | argmin (131072 as f32, if room) ]

typedef uint32_t u32;

#define B_    32
#define D_    64
#define K_    1024
#define HW_   4096
#define NPTS  (B_*HW_)
#define RES_ELEMS (B_*D_*HW_)

#define NT     256
#define PT     128
#define KTILE  128
#define NTILES (K_/KTILE)           // 8

// ---- screen smem ----
#define S_CSTRIDE 192
#define S_TILE (KTILE*S_CSTRIDE)    // 24576
#define S_OFF_SSQ  (2*S_TILE)
#define S_OFF_SIDX (S_OFF_SSQ + 4096)
#define S_OFF_FLAG (S_OFF_SIDX + 512)
#define S_SMEM (S_OFF_FLAG + 512)

// ---- rescue smem (hh tiles + fp32 x tile) ----
#define R_OFF_XS   (2*S_TILE)           // 49152: 128*68 floats = 34816
#define R_OFF_SSQ  (R_OFF_XS + 34816)   // 83968: 4096
#define R_OFF_IDS  (R_OFF_SSQ + 4096)   // 88064: 512
#define R_OFF_THR  (R_OFF_IDS + 512)    // 88576: 512
#define R_OFF_RIDX (R_OFF_THR + 512)    // 89088: 512
#define R_SMEM     (R_OFF_RIDX + 512)   // 89600

#define MARGIN_MUL 0.0022f
#define MARGIN_ADD 1e-4f

__device__ float4 g_hi[K_ * 8];     // hh cells (shared by screen + rescue)
__device__ float4 g_embT[K_ * 16];  // transposed fp32 codebook [k][d], 256 KB
__device__ float  g_ssq[K_];
__device__ float  g_emax;
__device__ int    g_nflag;
__device__ int    g_flag[NPTS];
__device__ float  g_thr[NPTS];

__device__ __forceinline__ u32 smem_u32(const void* p) {
    u32 a;
    asm("{ .reg .u64 t; cvta.to.shared.u64 t, %1; cvt.u32.u64 %0, t; }" : "=r"(a) : "l"(p));
    return a;
}
__device__ __forceinline__ u32 pack_h2(float a, float b) {
    __half2 p = __halves2half2(__float2half_rn(a), __float2half_rn(b));
    return *(u32*)&p;
}
__device__ __forceinline__ void mma16816(float& c0, float& c1, float& c2, float& c3,
                                         u32 a0, u32 a1, u32 a2, u32 a3, u32 b0, u32 b1) {
    asm("mma.sync.aligned.m16n8k16.row.col.f32.f16.f16.f32 "
        "{%0,%1,%2,%3}, {%4,%5,%6,%7}, {%8,%9}, {%0,%1,%2,%3};"
        : "+f"(c0), "+f"(c1), "+f"(c2), "+f"(c3)
        : "r"(a0), "r"(a1), "r"(a2), "r"(a3), "r"(b0), "r"(b1));
}
__device__ __forceinline__ void cp16(u32 dst, const void* src) {
    asm volatile("cp.async.cg.shared.global [%0], [%1], 16;" :: "r"(dst), "l"(src) : "memory");
}
__device__ __forceinline__ void cp_commit() {
    asm volatile("cp.async.commit_group;" ::: "memory");
}
template <int N> __device__ __forceinline__ void cp_wait() {
    asm volatile("cp.async.wait_group %0;" :: "n"(N) : "memory");
}

__global__ void zero_flags() { g_nflag = 0; g_emax = 0.f; }

__global__ void prep_all(const float* __restrict__ emb) {
    int id = blockIdx.x * 256 + threadIdx.x;       // 0..16383
    {   // embT cell: k = id>>4, float4 q = id&15 -> dims 4q..4q+3
        int k = id >> 4, q = id & 15;
        int d0 = q * 4;
        float4 cell;
        cell.x = emb[(d0    ) * K_ + k];
        cell.y = emb[(d0 + 1) * K_ + k];
        cell.z = emb[(d0 + 2) * K_ + k];
        cell.w = emb[(d0 + 3) * K_ + k];
        g_embT[id] = cell;
    }
    if (id < K_ * 8) {  // hh cell: [code][sp][tg], d0 = 32sp+2tg
        int n = id >> 3, r = id & 7;
        int sp = r >> 2, tg = r & 3;
        int d0 = 32 * sp + 2 * tg;
        float4 cell;
        cell.x = __uint_as_float(pack_h2(emb[(d0     ) * K_ + n], emb[(d0 +  1) * K_ + n]));
        cell.y = __uint_as_float(pack_h2(emb[(d0 +  8) * K_ + n], emb[(d0 +  9) * K_ + n]));
        cell.z = __uint_as_float(pack_h2(emb[(d0 + 16) * K_ + n], emb[(d0 + 17) * K_ + n]));
        cell.w = __uint_as_float(pack_h2(emb[(d0 + 24) * K_ + n], emb[(d0 + 25) * K_ + n]));
        g_hi[id] = cell;
    }
    if (id < K_) {
        float s = 0.f;
#pragma unroll
        for (int d = 0; d < D_; ++d) { float v = emb[d * K_ + id]; s = fmaf(v, v, s); }
        g_ssq[id] = s;
        atomicMax((int*)&g_emax, __float_as_int(s));
    }
}

#define UPD(bst, sec, bi, d, i) \
    do { if ((d) < (bst)) { sec = (bst); bst = (d); bi = (i); } \
         else if ((d) < (sec)) { sec = (d); } } while (0)

__global__ __launch_bounds__(NT, 2)
void vq_screen(const float* __restrict__ x, const float* __restrict__ emb,
               float* __restrict__ out, int out_size)
{
    extern __shared__ __align__(16) char smem[];
    const u32 sbase = smem_u32(smem);
    const int t = threadIdx.x;
    const int w = t >> 5, lane = t & 31;
    const int g = lane >> 2, tg = lane & 3;

    const int n0 = blockIdx.x * PT;
    const int bb = n0 >> 12, rem0 = n0 & 4095;
    const float* xblk = x + bb * (D_ * HW_) + rem0;

    {
        const char* src = (const char*)g_hi;
#pragma unroll
        for (int i = 0; i < 4; ++i) {
            int cell = t + 256 * i;
            int nl = cell >> 3, r = cell & 7;
            cp16(sbase + nl * S_CSTRIDE + r * 16, src + cell * 16);
        }
        cp_commit();
    }

    float* ssq_s = (float*)(smem + S_OFF_SSQ);
#pragma unroll
    for (int i = 0; i < 4; ++i) ssq_s[t + 256 * i] = g_ssq[t + 256 * i];

    const float emax = sqrtf(g_emax);

    u32 ah[4][4];
    float sxa = 0.f, sxb = 0.f;
    {
        const float* xw = xblk + w * 16;
#pragma unroll
        for (int s = 0; s < 4; ++s) {
            int d0 = 16 * s + 2 * tg;
            float v0a = xw[(d0    ) * HW_ + g],     v1a = xw[(d0 + 1) * HW_ + g];
            float v8a = xw[(d0 + 8) * HW_ + g],     v9a = xw[(d0 + 9) * HW_ + g];
            float v0b = xw[(d0    ) * HW_ + g + 8], v1b = xw[(d0 + 1) * HW_ + g + 8];
            float v8b = xw[(d0 + 8) * HW_ + g + 8], v9b = xw[(d0 + 9) * HW_ + g + 8];
            ah[s][0] = pack_h2(v0a, v1a);  ah[s][2] = pack_h2(v8a, v9a);
            ah[s][1] = pack_h2(v0b, v1b);  ah[s][3] = pack_h2(v8b, v9b);
            sxa = fmaf(v0a, v0a, fmaf(v1a, v1a, fmaf(v8a, v8a, fmaf(v9a, v9a, sxa))));
            sxb = fmaf(v0b, v0b, fmaf(v1b, v1b, fmaf(v8b, v8b, fmaf(v9b, v9b, sxb))));
        }
#pragma unroll
        for (int mask = 1; mask < 4; mask <<= 1) {
            sxa += __shfl_xor_sync(0xffffffffu, sxa, mask, 4);
            sxb += __shfl_xor_sync(0xffffffffu, sxb, mask, 4);
        }
    }

    float best0 = 3.402823e38f, sec0 = 3.402823e38f;
    float best1 = 3.402823e38f, sec1 = 3.402823e38f;
    int   bidx0 = 0, bidx1 = 0;

    for (int tile = 0; tile < NTILES; ++tile) {
        cp_wait<0>();
        __syncthreads();

        if (tile + 1 < NTILES) {
            const u32  nbuf = sbase + ((tile + 1) & 1) * S_TILE;
            const char* src = (const char*)g_hi + (tile + 1) * (KTILE * 128);
#pragma unroll
            for (int i = 0; i < 4; ++i) {
                int cell = t + 256 * i;
                int nl = cell >> 3, r = cell & 7;
                cp16(nbuf + nl * S_CSTRIDE + r * 16, src + cell * 16);
            }
            cp_commit();
        }

        const char* bufc = smem + (tile & 1) * S_TILE;
        const float2* sq2 = (const float2*)ssq_s;
#pragma unroll 2
        for (int pair = 0; pair < 8; ++pair) {
            const float4* bpA = (const float4*)(bufc + (pair * 16 + g)     * S_CSTRIDE + tg * 16);
            const float4* bpB = (const float4*)(bufc + (pair * 16 + 8 + g) * S_CSTRIDE + tg * 16);
            float4 A0 = bpA[0], A1 = bpA[4];
            float4 B0 = bpB[0], B1 = bpB[4];
            float a0=0.f,a1=0.f,a2=0.f,a3=0.f, b0=0.f,b1=0.f,b2=0.f,b3=0.f;
            mma16816(a0,a1,a2,a3, ah[0][0],ah[0][1],ah[0][2],ah[0][3],
                     __float_as_uint(A0.x), __float_as_uint(A0.y));
            mma16816(b0,b1,b2,b3, ah[0][0],ah[0][1],ah[0][2],ah[0][3],
                     __float_as_uint(B0.x), __float_as_uint(B0.y));
            mma16816(a0,a1,a2,a3, ah[1][0],ah[1][1],ah[1][2],ah[1][3],
                     __float_as_uint(A0.z), __float_as_uint(A0.w));
            mma16816(b0,b1,b2,b3, ah[1][0],ah[1][1],ah[1][2],ah[1][3],
                     __float_as_uint(B0.z), __float_as_uint(B0.w));
            mma16816(a0,a1,a2,a3, ah[2][0],ah[2][1],ah[2][2],ah[2][3],
                     __float_as_uint(A1.x), __float_as_uint(A1.y));
            mma16816(b0,b1,b2,b3, ah[2][0],ah[2][1],ah[2][2],ah[2][3],
                     __float_as_uint(B1.x), __float_as_uint(B1.y));
            mma16816(a0,a1,a2,a3, ah[3][0],ah[3][1],ah[3][2],ah[3][3],
                     __float_as_uint(A1.z), __float_as_uint(A1.w));
            mma16816(b0,b1,b2,b3, ah[3][0],ah[3][1],ah[3][2],ah[3][3],
                     __float_as_uint(B1.z), __float_as_uint(B1.w));

            const int kgA = tile * KTILE + pair * 16 + 2 * tg;
            const int kgB = kgA + 8;
            const float2 sqA = sq2[kgA >> 1];
            const float2 sqB = sq2[kgB >> 1];
            float dA0 = fmaf(-2.f, a0, sqA.x);
            float dA1 = fmaf(-2.f, a1, sqA.y);
            float dA2 = fmaf(-2.f, a2, sqA.x);
            float dA3 = fmaf(-2.f, a3, sqA.y);
            float dB0 = fmaf(-2.f, b0, sqB.x);
            float dB1 = fmaf(-2.f, b1, sqB.y);
            float dB2 = fmaf(-2.f, b2, sqB.x);
            float dB3 = fmaf(-2.f, b3, sqB.y);
            UPD(best0, sec0, bidx0, dA0, kgA);
            UPD(best0, sec0, bidx0, dA1, kgA + 1);
            UPD(best0, sec0, bidx0, dB0, kgB);
            UPD(best0, sec0, bidx0, dB1, kgB + 1);
            UPD(best1, sec1, bidx1, dA2, kgA);
            UPD(best1, sec1, bidx1, dA3, kgA + 1);
            UPD(best1, sec1, bidx1, dB2, kgB);
            UPD(best1, sec1, bidx1, dB3, kgB + 1);
        }
    }

#pragma unroll
    for (int mask = 1; mask < 4; mask <<= 1) {
        float ob = __shfl_xor_sync(0xffffffffu, best0, mask, 4);
        int   oi = __shfl_xor_sync(0xffffffffu, bidx0, mask, 4);
        float os = __shfl_xor_sync(0xffffffffu, sec0,  mask, 4);
        if (ob < best0 || (ob == best0 && oi < bidx0)) {
            sec0 = fminf(best0, fminf(os, sec0)); best0 = ob; bidx0 = oi;
        } else sec0 = fminf(sec0, fminf(ob, os));
        ob = __shfl_xor_sync(0xffffffffu, best1, mask, 4);
        oi = __shfl_xor_sync(0xffffffffu, bidx1, mask, 4);
        os = __shfl_xor_sync(0xffffffffu, sec1,  mask, 4);
        if (ob < best1 || (ob == best1 && oi < bidx1)) {
            sec1 = fminf(best1, fminf(os, sec1)); best1 = ob; bidx1 = oi;
        } else sec1 = fminf(sec1, fminf(ob, os));
    }

    int*  sidx  = (int*)(smem + S_OFF_SIDX);
    char* sflag = (char*)(smem + S_OFF_FLAG);
    if (tg == 0) {
        sidx[w * 16 + g]     = bidx0;
        sidx[w * 16 + 8 + g] = bidx1;
        float m0 = fmaf(MARGIN_MUL * emax, sqrtf(sxa), MARGIN_ADD);
        float m1 = fmaf(MARGIN_MUL * emax, sqrtf(sxb), MARGIN_ADD);
        int f0 = (sec0 - best0 < m0);
        int f1 = (sec1 - best1 < m1);
        sflag[w * 16 + g]     = (char)f0;
        sflag[w * 16 + 8 + g] = (char)f1;
        if (f0) { int s = atomicAdd(&g_nflag, 1); g_flag[s] = n0 + w * 16 + g;
                  g_thr[s] = best0 + m0; }
        if (f1) { int s = atomicAdd(&g_nflag, 1); g_flag[s] = n0 + w * 16 + 8 + g;
                  g_thr[s] = best1 + m1; }
    }
    __syncthreads();

    if (t < PT && out_size >= RES_ELEMS + NPTS)
        out[RES_ELEMS + n0 + t] = (float)sidx[t];

    float* ob2 = out + bb * (D_ * HW_) + rem0;
#pragma unroll 8
    for (int i = 0; i < 32; ++i) {
        int flat = t + NT * i;
        int p = flat & 127, d = flat >> 7;
        if (!sflag[p])
            ob2[d * HW_ + p] = __ldg(&emb[d * K_ + sidx[p]]);
    }
}

// exact fp32 re-score of candidate k against xs row; ascending-k callers: strict '<'
__device__ __forceinline__ void exact_upd(const float* xsrow, int k, const float* ssq_s,
                                          float& eb, int& ei) {
    const float4* xv = (const float4*)xsrow;
    const float4* ev = &g_embT[k * 16];
    float s0 = 0.f, s1 = 0.f, s2 = 0.f, s3 = 0.f;
#pragma unroll
    for (int i = 0; i < 16; i += 4) {
        float4 xa = xv[i],   ea = __ldg(&ev[i]);
        float4 xb = xv[i+1], eb4 = __ldg(&ev[i+1]);
        float4 xc = xv[i+2], ec = __ldg(&ev[i+2]);
        float4 xd = xv[i+3], ed = __ldg(&ev[i+3]);
        s0 = fmaf(xa.x, ea.x, fmaf(xa.y, ea.y, fmaf(xa.z, ea.z, fmaf(xa.w, ea.w, s0))));
        s1 = fmaf(xb.x, eb4.x, fmaf(xb.y, eb4.y, fmaf(xb.z, eb4.z, fmaf(xb.w, eb4.w, s1))));
        s2 = fmaf(xc.x, ec.x, fmaf(xc.y, ec.y, fmaf(xc.z, ec.z, fmaf(xc.w, ec.w, s2))));
        s3 = fmaf(xd.x, ed.x, fmaf(xd.y, ed.y, fmaf(xd.z, ed.z, fmaf(xd.w, ed.w, s3))));
    }
    float d = fmaf(-2.f, (s0 + s1) + (s2 + s3), ssq_s[k]);
    if (d < eb) { eb = d; ei = k; }
}

__global__ __launch_bounds__(NT, 2)
void vq_rescue(const float* __restrict__ x, const float* __restrict__ emb,
               float* __restrict__ out, int out_size)
{
    extern __shared__ __align__(16) char smem[];
    const u32 sbase = smem_u32(smem);
    const int t = threadIdx.x;
    const int w = t >> 5, lane = t & 31;
    const int g = lane >> 2, tg = lane & 3;
    const int cnt = g_nflag;

    if (blockIdx.x * PT >= cnt) return;

    float* ssq_s = (float*)(smem + R_OFF_SSQ);
#pragma unroll
    for (int i = 0; i < 4; ++i) ssq_s[t + 256 * i] = g_ssq[t + 256 * i];
    int*   sids = (int*)(smem + R_OFF_IDS);
    float* sthr = (float*)(smem + R_OFF_THR);
    int*   ridx = (int*)(smem + R_OFF_RIDX);
    float* xs   = (float*)(smem + R_OFF_XS);

    for (int base = blockIdx.x * PT; base < cnt; base += gridDim.x * PT) {
        const int m = min(PT, cnt - base);
        if (t < PT) {
            int ii = base + min(t, m - 1);
            sids[t] = g_flag[ii];
            sthr[t] = g_thr[ii];
        }
        __syncthreads();

        // gather fp32 x for the 128 points into smem (2 threads/point, 32 dims each)
        {
            int p = t & 127, dh = t >> 7;
            int n = sids[p];
            const float* xp = x + (n >> 12) * (D_ * HW_) + (n & 4095);
#pragma unroll 8
            for (int i = 0; i < 32; ++i) {
                int d = dh * 32 + i;
                xs[p * 68 + d] = xp[d * HW_];
            }
        }
        // prefetch hh tile 0
        {
            const char* src = (const char*)g_hi;
#pragma unroll
            for (int i = 0; i < 4; ++i) {
                int cell = t + 256 * i;
                int nl = cell >> 3, r = cell & 7;
                cp16(sbase + nl * S_CSTRIDE + r * 16, src + cell * 16);
            }
            cp_commit();
        }
        __syncthreads();   // xs ready

        // build hh A fragments from xs (bitwise same conversion as screen)
        const float* xs0 = xs + (w * 16 + g) * 68;
        const float* xs1 = xs + (w * 16 + 8 + g) * 68;
        u32 ah[4][4];
#pragma unroll
        for (int s = 0; s < 4; ++s) {
            int d0 = 16 * s + 2 * tg;
            ah[s][0] = pack_h2(xs0[d0],     xs0[d0 + 1]);
            ah[s][2] = pack_h2(xs0[d0 + 8], xs0[d0 + 9]);
            ah[s][1] = pack_h2(xs1[d0],     xs1[d0 + 1]);
            ah[s][3] = pack_h2(xs1[d0 + 8], xs1[d0 + 9]);
        }
        const float thr0 = sthr[w * 16 + g];
        const float thr1 = sthr[w * 16 + 8 + g];

        float eb0 = 3.402823e38f, eb1 = 3.402823e38f;
        int   ei0 = 0, ei1 = 0;

        for (int tile = 0; tile < NTILES; ++tile) {
            cp_wait<0>();
            __syncthreads();
            if (tile + 1 < NTILES) {
                const u32  nbuf = sbase + ((tile + 1) & 1) * S_TILE;
                const char* src = (const char*)g_hi + (tile + 1) * (KTILE * 128);
#pragma unroll
                for (int i = 0; i < 4; ++i) {
                    int cell = t + 256 * i;
                    int nl = cell >> 3, r = cell & 7;
                    cp16(nbuf + nl * S_CSTRIDE + r * 16, src + cell * 16);
                }
                cp_commit();
            }
            const char* bufc = smem + (tile & 1) * S_TILE;
#pragma unroll 2
            for (int pair = 0; pair < 8; ++pair) {
                const float4* bpA = (const float4*)(bufc + (pair * 16 + g)     * S_CSTRIDE + tg * 16);
                const float4* bpB = (const float4*)(bufc + (pair * 16 + 8 + g) * S_CSTRIDE + tg * 16);
                float4 A0 = bpA[0], A1 = bpA[4];
                float4 B0 = bpB[0], B1 = bpB[4];
                float a0=0.f,a1=0.f,a2=0.f,a3=0.f, b0=0.f,b1=0.f,b2=0.f,b3=0.f;
                // IDENTICAL chain order to vq_screen -> bitwise-identical d~
                mma16816(a0,a1,a2,a3, ah[0][0],ah[0][1],ah[0][2],ah[0][3],
                         __float_as_uint(A0.x), __float_as_uint(A0.y));
                mma16816(b0,b1,b2,b3, ah[0][0],ah[0][1],ah[0][2],ah[0][3],
                         __float_as_uint(B0.x), __float_as_uint(B0.y));
                mma16816(a0,a1,a2,a3, ah[1][0],ah[1][1],ah[1][2],ah[1][3],
                         __float_as_uint(A0.z), __float_as_uint(A0.w));
                mma16816(b0,b1,b2,b3, ah[1][0],ah[1][1],ah[1][2],ah[1][3],
                         __float_as_uint(B0.z), __float_as_uint(B0.w));
                mma16816(a0,a1,a2,a3, ah[2][0],ah[2][1],ah[2][2],ah[2][3],
                         __float_as_uint(A1.x), __float_as_uint(A1.y));
                mma16816(b0,b1,b2,b3, ah[2][0],ah[2][1],ah[2][2],ah[2][3],
                         __float_as_uint(B1.x), __float_as_uint(B1.y));
                mma16816(a0,a1,a2,a3, ah[3][0],ah[3][1],ah[3][2],ah[3][3],
                         __float_as_uint(A1.z), __float_as_uint(A1.w));
                mma16816(b0,b1,b2,b3, ah[3][0],ah[3][1],ah[3][2],ah[3][3],
                         __float_as_uint(B1.z), __float_as_uint(B1.w));

                const int kgA = tile * KTILE + pair * 16 + 2 * tg;
                const int kgB = kgA + 8;
                float dA0 = fmaf(-2.f, a0, ssq_s[kgA]);
                float dA1 = fmaf(-2.f, a1, ssq_s[kgA + 1]);
                float dA2 = fmaf(-2.f, a2, ssq_s[kgA]);
                float dA3 = fmaf(-2.f, a3, ssq_s[kgA + 1]);
                float dB0 = fmaf(-2.f, b0, ssq_s[kgB]);
                float dB1 = fmaf(-2.f, b1, ssq_s[kgB + 1]);
                float dB2 = fmaf(-2.f, b2, ssq_s[kgB]);
                float dB3 = fmaf(-2.f, b3, ssq_s[kgB + 1]);
                // candidates: approx within threshold -> exact fp32 re-score (rare)
                if (dA0 < thr0) exact_upd(xs0, kgA,     ssq_s, eb0, ei0);
                if (dA1 < thr0) exact_upd(xs0, kgA + 1, ssq_s, eb0, ei0);
                if (dB0 < thr0) exact_upd(xs0, kgB,     ssq_s, eb0, ei0);
                if (dB1 < thr0) exact_upd(xs0, kgB + 1, ssq_s, eb0, ei0);
                if (dA2 < thr1) exact_upd(xs1, kgA,     ssq_s, eb1, ei1);
                if (dA3 < thr1) exact_upd(xs1, kgA + 1, ssq_s, eb1, ei1);
                if (dB2 < thr1) exact_upd(xs1, kgB,     ssq_s, eb1, ei1);
                if (dB3 < thr1) exact_upd(xs1, kgB + 1, ssq_s, eb1, ei1);
            }
        }

        // merge exact results across the 4 tg lanes (tie -> smaller index)
#pragma unroll
        for (int mask = 1; mask < 4; mask <<= 1) {
            float e0 = __shfl_xor_sync(0xffffffffu, eb0, mask, 4);
            int   j0 = __shfl_xor_sync(0xffffffffu, ei0, mask, 4);
            if (e0 < eb0 || (e0 == eb0 && j0 < ei0)) { eb0 = e0; ei0 = j0; }
            float e1 = __shfl_xor_sync(0xffffffffu, eb1, mask, 4);
            int   j1 = __shfl_xor_sync(0xffffffffu, ei1, mask, 4);
            if (e1 < eb1 || (e1 == eb1 && j1 < ei1)) { eb1 = e1; ei1 = j1; }
        }
        if (tg == 0) {
            ridx[w * 16 + g]     = ei0;
            ridx[w * 16 + 8 + g] = ei1;
        }
        __syncthreads();

        for (int i = t; i < m * 64; i += NT) {
            int pl = i >> 6, d = i & 63;
            int n = sids[pl], b = n >> 12, rem = n & 4095;
            out[b * (D_ * HW_) + d * HW_ + rem] = __ldg(&emb[d * K_ + ridx[pl]]);
        }
        if (t < m && out_size >= RES_ELEMS + NPTS)
            out[RES_ELEMS + sids[t]] = (float)ridx[t];
        __syncthreads();
    }
}

extern "C" void kernel_launch(void* const* d_in, const int* in_sizes, int n_in,
                              void* d_out, int out_size)
{
    const float* x   = (const float*)d_in[0];
    const float* emb = (const float*)d_in[1];
    if (n_in >= 2 && in_sizes[0] == D_ * K_ && in_sizes[1] == RES_ELEMS) {
        x   = (const float*)d_in[1];
        emb = (const float*)d_in[0];
    }
    static int configured = 0;
    if (!configured) {
        cudaFuncSetAttribute(vq_screen, cudaFuncAttributeMaxDynamicSharedMemorySize, S_SMEM);
        cudaFuncSetAttribute(vq_rescue, cudaFuncAttributeMaxDynamicSharedMemorySize, R_SMEM);
        configured = 1;
    }
    zero_flags<<<1, 1>>>();
    prep_all<<<64, 256>>>(emb);
    vq_screen<<<NPTS / PT, NT, S_SMEM>>>(x, emb, (float*)d_out, out_size);
    vq_rescue<<<1024, NT, R_SMEM>>>(x, emb, (float*)d_out, out_size);
}

// round 16
// speedup vs baseline: 1.1684x; 1.1684x over previous
#include <cuda_runtime.h>
#include <cuda_fp16.h>
#include <cstdint>

// NearestEmbed (VQ): fp16 hh MMA screen + R14 3-chain fp16-split MMA rescue.
// R16: screen selection via bit-packed keys (FMNMX top-2, no predicate chains);
// ties are always flagged, so screen tie-direction is immaterial.
// x [32,64,64,64] f32, emb [64,1024] f32
// out = [ result (8388608 f32) | argmin (131072 as f32, if room) ]

typedef uint32_t u32;

#define B_    32
#define D_    64
#define K_    1024
#define HW_   4096
#define NPTS  (B_*HW_)
#define RES_ELEMS (B_*D_*HW_)

#define NT     256
#define PT     128
#define KTILE  128
#define NTILES (K_/KTILE)           // 8

// ---- screen smem ----
#define S_CSTRIDE 192
#define S_TILE (KTILE*S_CSTRIDE)    // 24576
#define S_OFF_SSQ  (2*S_TILE)
#define S_OFF_SIDX (S_OFF_SSQ + 4096)
#define S_OFF_FLAG (S_OFF_SIDX + 512)
#define S_SMEM (S_OFF_FLAG + 512)

// ---- rescue smem ----
#define R_CSTRIDE 320
#define R_TILE (KTILE*R_CSTRIDE)    // 40960
#define R_OFF_SSQ  (2*R_TILE)
#define R_OFF_IDS  (R_OFF_SSQ + 4096)
#define R_OFF_RIDX (R_OFF_IDS + 512)
#define R_SMEM (R_OFF_RIDX + 512)   // 87040

#define MARGIN_MUL 0.0022f
#define MARGIN_ADD 0.0051f          // 1e-4 + 8-bit key-packing slack
#define LO_SCALE   2048.0f
#define NEG2LO     (-2.0f/2048.0f)

__device__ float4 g_hi[K_ * 8];     // hh cells (screen)
__device__ float4 g_hl[K_ * 16];    // hi+scaled-lo cells (rescue)
__device__ float  g_ssq[K_];
__device__ float  g_emax;
__device__ int    g_nflag;
__device__ int    g_flag[NPTS];

__device__ __forceinline__ u32 smem_u32(const void* p) {
    u32 a;
    asm("{ .reg .u64 t; cvta.to.shared.u64 t, %1; cvt.u32.u64 %0, t; }" : "=r"(a) : "l"(p));
    return a;
}
__device__ __forceinline__ u32 pack_h2(float a, float b) {
    __half2 p = __halves2half2(__float2half_rn(a), __float2half_rn(b));
    return *(u32*)&p;
}
__device__ __forceinline__ void split_h(float v, __half& h, __half& l) {
    h = __float2half_rn(v);
    l = __float2half_rn((v - __half2float(h)) * LO_SCALE);
}
__device__ __forceinline__ u32 pack2(__half a, __half b) {
    __half2 p = __halves2half2(a, b);
    return *(u32*)&p;
}
__device__ __forceinline__ void mma16816(float& c0, float& c1, float& c2, float& c3,
                                         u32 a0, u32 a1, u32 a2, u32 a3, u32 b0, u32 b1) {
    asm("mma.sync.aligned.m16n8k16.row.col.f32.f16.f16.f32 "
        "{%0,%1,%2,%3}, {%4,%5,%6,%7}, {%8,%9}, {%0,%1,%2,%3};"
        : "+f"(c0), "+f"(c1), "+f"(c2), "+f"(c3)
        : "r"(a0), "r"(a1), "r"(a2), "r"(a3), "r"(b0), "r"(b1));
}
__device__ __forceinline__ void cp16(u32 dst, const void* src) {
    asm volatile("cp.async.cg.shared.global [%0], [%1], 16;" :: "r"(dst), "l"(src) : "memory");
}
__device__ __forceinline__ void cp_commit() {
    asm volatile("cp.async.commit_group;" ::: "memory");
}
template <int N> __device__ __forceinline__ void cp_wait() {
    asm volatile("cp.async.wait_group %0;" :: "n"(N) : "memory");
}

__global__ void zero_flags() { g_nflag = 0; g_emax = 0.f; }

__global__ void prep_all(const float* __restrict__ emb) {
    int id = blockIdx.x * 256 + threadIdx.x;       // 0..16383
    {   // HL cell: [code][s][tg], d0 = 16s+2tg
        int n = id >> 4, r = id & 15;
        int s = r >> 2, tg = r & 3;
        int d0 = 16 * s + 2 * tg;
        __half h0,l0,h1,l1,h8,l8,h9,l9;
        split_h(emb[(d0    ) * K_ + n], h0, l0);
        split_h(emb[(d0 + 1) * K_ + n], h1, l1);
        split_h(emb[(d0 + 8) * K_ + n], h8, l8);
        split_h(emb[(d0 + 9) * K_ + n], h9, l9);
        float4 cell;
        cell.x = __uint_as_float(pack2(h0, h1));
        cell.y = __uint_as_float(pack2(h8, h9));
        cell.z = __uint_as_float(pack2(l0, l1));
        cell.w = __uint_as_float(pack2(l8, l9));
        g_hl[id] = cell;
    }
    if (id < K_ * 8) {  // hh cell: [code][sp][tg], d0 = 32sp+2tg
        int n = id >> 3, r = id & 7;
        int sp = r >> 2, tg = r & 3;
        int d0 = 32 * sp + 2 * tg;
        float4 cell;
        cell.x = __uint_as_float(pack_h2(emb[(d0     ) * K_ + n], emb[(d0 +  1) * K_ + n]));
        cell.y = __uint_as_float(pack_h2(emb[(d0 +  8) * K_ + n], emb[(d0 +  9) * K_ + n]));
        cell.z = __uint_as_float(pack_h2(emb[(d0 + 16) * K_ + n], emb[(d0 + 17) * K_ + n]));
        cell.w = __uint_as_float(pack_h2(emb[(d0 + 24) * K_ + n], emb[(d0 + 25) * K_ + n]));
        g_hi[id] = cell;
    }
    if (id < K_) {
        float s = 0.f;
#pragma unroll
        for (int d = 0; d < D_; ++d) { float v = emb[d * K_ + id]; s = fmaf(v, v, s); }
        g_ssq[id] = s;
        atomicMax((int*)&g_emax, __float_as_int(s));
    }
}

// packed key: s-value with low 8 mantissa bits replaced by (tile<<5)|(pair<<2)|slot
#define PKEY(sv, pc) __uint_as_float((__float_as_uint(sv) & 0xFFFFFF00u) | (u32)(pc))
#define TOP2(best, sec, key) do { float _t = fminf(best, key); \
    best = fmaxf(best, key); sec = fmaxf(sec, _t); } while (0)

__global__ __launch_bounds__(NT, 2)
void vq_screen(const float* __restrict__ x, const float* __restrict__ emb,
               float* __restrict__ out, int out_size)
{
    extern __shared__ __align__(16) char smem[];
    const u32 sbase = smem_u32(smem);
    const int t = threadIdx.x;
    const int w = t >> 5, lane = t & 31;
    const int g = lane >> 2, tg = lane & 3;

    const int n0 = blockIdx.x * PT;
    const int bb = n0 >> 12, rem0 = n0 & 4095;
    const float* xblk = x + bb * (D_ * HW_) + rem0;

    {
        const char* src = (const char*)g_hi;
#pragma unroll
        for (int i = 0; i < 4; ++i) {
            int cell = t + 256 * i;
            int nl = cell >> 3, r = cell & 7;
            cp16(sbase + nl * S_CSTRIDE + r * 16, src + cell * 16);
        }
        cp_commit();
    }

    float* ssq_s = (float*)(smem + S_OFF_SSQ);     // halved: s = dot - ssq/2
#pragma unroll
    for (int i = 0; i < 4; ++i) ssq_s[t + 256 * i] = 0.5f * g_ssq[t + 256 * i];

    const float emax = sqrtf(g_emax);

    u32 ah[4][4];
    float sxa = 0.f, sxb = 0.f;
    {
        const float* xw = xblk + w * 16;
#pragma unroll
        for (int s = 0; s < 4; ++s) {
            int d0 = 16 * s + 2 * tg;
            float v0a = xw[(d0    ) * HW_ + g],     v1a = xw[(d0 + 1) * HW_ + g];
            float v8a = xw[(d0 + 8) * HW_ + g],     v9a = xw[(d0 + 9) * HW_ + g];
            float v0b = xw[(d0    ) * HW_ + g + 8], v1b = xw[(d0 + 1) * HW_ + g + 8];
            float v8b = xw[(d0 + 8) * HW_ + g + 8], v9b = xw[(d0 + 9) * HW_ + g + 8];
            ah[s][0] = pack_h2(v0a, v1a);  ah[s][2] = pack_h2(v8a, v9a);
            ah[s][1] = pack_h2(v0b, v1b);  ah[s][3] = pack_h2(v8b, v9b);
            sxa = fmaf(v0a, v0a, fmaf(v1a, v1a, fmaf(v8a, v8a, fmaf(v9a, v9a, sxa))));
            sxb = fmaf(v0b, v0b, fmaf(v1b, v1b, fmaf(v8b, v8b, fmaf(v9b, v9b, sxb))));
        }
#pragma unroll
        for (int mask = 1; mask < 4; mask <<= 1) {
            sxa += __shfl_xor_sync(0xffffffffu, sxa, mask, 4);
            sxb += __shfl_xor_sync(0xffffffffu, sxb, mask, 4);
        }
    }

    // packed argmax of s = dot - ssq/2 (equiv. argmin dist); ties always flagged
    float best0 = -3.402823e38f, sec0 = -3.402823e38f;
    float best1 = -3.402823e38f, sec1 = -3.402823e38f;

    for (int tile = 0; tile < NTILES; ++tile) {
        cp_wait<0>();
        __syncthreads();

        if (tile + 1 < NTILES) {
            const u32  nbuf = sbase + ((tile + 1) & 1) * S_TILE;
            const char* src = (const char*)g_hi + (tile + 1) * (KTILE * 128);
#pragma unroll
            for (int i = 0; i < 4; ++i) {
                int cell = t + 256 * i;
                int nl = cell >> 3, r = cell & 7;
                cp16(nbuf + nl * S_CSTRIDE + r * 16, src + cell * 16);
            }
            cp_commit();
        }

        const char* bufc = smem + (tile & 1) * S_TILE;
        const float2* sq2 = (const float2*)ssq_s;
#pragma unroll 2
        for (int pair = 0; pair < 8; ++pair) {
            const float4* bpA = (const float4*)(bufc + (pair * 16 + g)     * S_CSTRIDE + tg * 16);
            const float4* bpB = (const float4*)(bufc + (pair * 16 + 8 + g) * S_CSTRIDE + tg * 16);
            float4 A0 = bpA[0], A1 = bpA[4];
            float4 B0 = bpB[0], B1 = bpB[4];
            float a0=0.f,a1=0.f,a2=0.f,a3=0.f, b0=0.f,b1=0.f,b2=0.f,b3=0.f;
            mma16816(a0,a1,a2,a3, ah[0][0],ah[0][1],ah[0][2],ah[0][3],
                     __float_as_uint(A0.x), __float_as_uint(A0.y));
            mma16816(b0,b1,b2,b3, ah[0][0],ah[0][1],ah[0][2],ah[0][3],
                     __float_as_uint(B0.x), __float_as_uint(B0.y));
            mma16816(a0,a1,a2,a3, ah[1][0],ah[1][1],ah[1][2],ah[1][3],
                     __float_as_uint(A0.z), __float_as_uint(A0.w));
            mma16816(b0,b1,b2,b3, ah[1][0],ah[1][1],ah[1][2],ah[1][3],
                     __float_as_uint(B0.z), __float_as_uint(B0.w));
            mma16816(a0,a1,a2,a3, ah[2][0],ah[2][1],ah[2][2],ah[2][3],
                     __float_as_uint(A1.x), __float_as_uint(A1.y));
            mma16816(b0,b1,b2,b3, ah[2][0],ah[2][1],ah[2][2],ah[2][3],
                     __float_as_uint(B1.x), __float_as_uint(B1.y));
            mma16816(a0,a1,a2,a3, ah[3][0],ah[3][1],ah[3][2],ah[3][3],
                     __float_as_uint(A1.z), __float_as_uint(A1.w));
            mma16816(b0,b1,b2,b3, ah[3][0],ah[3][1],ah[3][2],ah[3][3],
                     __float_as_uint(B1.z), __float_as_uint(B1.w));

            const int kgA = tile * KTILE + pair * 16 + 2 * tg;
            const int kgB = kgA + 8;
            const float2 sqA = sq2[kgA >> 1];
            const float2 sqB = sq2[kgB >> 1];
            const int pc = (tile << 5) | (pair << 2);   // slot: 0,1 -> A; 2,3 -> B
            // point 0
            TOP2(best0, sec0, PKEY(a0 - sqA.x, pc    ));
            TOP2(best0, sec0, PKEY(a1 - sqA.y, pc + 1));
            TOP2(best0, sec0, PKEY(b0 - sqB.x, pc + 2));
            TOP2(best0, sec0, PKEY(b1 - sqB.y, pc + 3));
            // point 1
            TOP2(best1, sec1, PKEY(a2 - sqA.x, pc    ));
            TOP2(best1, sec1, PKEY(a3 - sqA.y, pc + 1));
            TOP2(best1, sec1, PKEY(b2 - sqB.x, pc + 2));
            TOP2(best1, sec1, PKEY(b3 - sqB.y, pc + 3));
        }
    }

    // decode own best (tg needed), then merge across the 4 tg-lanes per point
    int idx0, idx1;
    {
        u32 p0 = __float_as_uint(best0) & 255u;
        u32 p1 = __float_as_uint(best1) & 255u;
        int s0 = p0 & 3, s1 = p1 & 3;
        idx0 = (int)((p0 >> 5) << 7) + (int)(((p0 >> 2) & 7) << 4) + 2 * tg + s0 + (s0 >> 1) * 6;
        idx1 = (int)((p1 >> 5) << 7) + (int)(((p1 >> 2) & 7) << 4) + 2 * tg + s1 + (s1 >> 1) * 6;
    }
#pragma unroll
    for (int mask = 1; mask < 4; mask <<= 1) {
        float ob = __shfl_xor_sync(0xffffffffu, best0, mask, 4);
        int   oi = __shfl_xor_sync(0xffffffffu, idx0,  mask, 4);
        float os = __shfl_xor_sync(0xffffffffu, sec0,  mask, 4);
        float mn = fminf(best0, ob);
        if (ob > best0) { best0 = ob; idx0 = oi; }      // exact tie -> flagged anyway
        sec0 = fmaxf(fmaxf(sec0, os), mn);
        ob = __shfl_xor_sync(0xffffffffu, best1, mask, 4);
        oi = __shfl_xor_sync(0xffffffffu, idx1,  mask, 4);
        os = __shfl_xor_sync(0xffffffffu, sec1,  mask, 4);
        mn = fminf(best1, ob);
        if (ob > best1) { best1 = ob; idx1 = oi; }
        sec1 = fmaxf(fmaxf(sec1, os), mn);
    }

    int*  sidx  = (int*)(smem + S_OFF_SIDX);
    char* sflag = (char*)(smem + S_OFF_FLAG);
    if (tg == 0) {
        sidx[w * 16 + g]     = idx0;
        sidx[w * 16 + 8 + g] = idx1;
        // gap in d-units = 2*(best - sec); flag if < margin
        float m0 = fmaf(MARGIN_MUL * emax, sqrtf(sxa), MARGIN_ADD) * 0.5f;
        float m1 = fmaf(MARGIN_MUL * emax, sqrtf(sxb), MARGIN_ADD) * 0.5f;
        int f0 = (best0 - sec0 < m0);
        int f1 = (best1 - sec1 < m1);
        sflag[w * 16 + g]     = (char)f0;
        sflag[w * 16 + 8 + g] = (char)f1;
        if (f0) { int s = atomicAdd(&g_nflag, 1); g_flag[s] = n0 + w * 16 + g; }
        if (f1) { int s = atomicAdd(&g_nflag, 1); g_flag[s] = n0 + w * 16 + 8 + g; }
    }
    __syncthreads();

    if (t < PT && out_size >= RES_ELEMS + NPTS)
        out[RES_ELEMS + n0 + t] = (float)sidx[t];

    // gather code vectors; skip flagged points (rescue overwrites them)
    float* ob2 = out + bb * (D_ * HW_) + rem0;
#pragma unroll 8
    for (int i = 0; i < 32; ++i) {
        int flat = t + NT * i;
        int p = flat & 127, d = flat >> 7;
        if (!sflag[p])
            ob2[d * HW_ + p] = __ldg(&emb[d * K_ + sidx[p]]);
    }
}

// ---- MMA rescue: exact R10/R14 3-chain arithmetic on gathered flagged points ----
__global__ __launch_bounds__(NT, 2)
void vq_rescue(const float* __restrict__ x, const float* __restrict__ emb,
               float* __restrict__ out, int out_size)
{
    extern __shared__ __align__(16) char smem[];
    const u32 sbase = smem_u32(smem);
    const int t = threadIdx.x;
    const int w = t >> 5, lane = t & 31;
    const int g = lane >> 2, tg = lane & 3;
    const int cnt = g_nflag;

    if (blockIdx.x * PT >= cnt) return;

    float* ssq_s = (float*)(smem + R_OFF_SSQ);
#pragma unroll
    for (int i = 0; i < 4; ++i) ssq_s[t + 256 * i] = g_ssq[t + 256 * i];
    int* sids = (int*)(smem + R_OFF_IDS);
    int* ridx = (int*)(smem + R_OFF_RIDX);

    for (int base = blockIdx.x * PT; base < cnt; base += gridDim.x * PT) {
        const int m = min(PT, cnt - base);
        if (t < PT) sids[t] = g_flag[base + min(t, m - 1)];
        __syncthreads();

        float va[8], vb[8];
        {
            int na = sids[w * 16 + g], nb = sids[w * 16 + 8 + g];
            const float* pa = x + (na >> 12) * (D_ * HW_) + (na & 4095);
            const float* pb = x + (nb >> 12) * (D_ * HW_) + (nb & 4095);
#pragma unroll
            for (int s = 0; s < 4; ++s) {
                int d0 = 16 * s + 2 * tg;
                va[2*s]   = pa[(d0    ) * HW_];
                vb[2*s]   = pb[(d0    ) * HW_];
                va[2*s+1] = pa[(d0 + 8) * HW_];
                vb[2*s+1] = pb[(d0 + 8) * HW_];
            }
        }
        float wa[8], wb[8];
        {
            int na = sids[w * 16 + g], nb = sids[w * 16 + 8 + g];
            const float* pa = x + (na >> 12) * (D_ * HW_) + (na & 4095);
            const float* pb = x + (nb >> 12) * (D_ * HW_) + (nb & 4095);
#pragma unroll
            for (int s = 0; s < 4; ++s) {
                int d0 = 16 * s + 2 * tg;
                wa[2*s]   = pa[(d0 + 1) * HW_];
                wb[2*s]   = pb[(d0 + 1) * HW_];
                wa[2*s+1] = pa[(d0 + 9) * HW_];
                wb[2*s+1] = pb[(d0 + 9) * HW_];
            }
        }
        {
            const char* src = (const char*)g_hl;
#pragma unroll
            for (int i = 0; i < 8; ++i) {
                int cell = t + 256 * i;
                int nl = cell >> 4, r = cell & 15;
                cp16(sbase + nl * R_CSTRIDE + r * 16, src + cell * 16);
            }
            cp_commit();
        }

        u32 ah[4][4], al[4][4];
#pragma unroll
        for (int s = 0; s < 4; ++s) {
            __half h0a,l0a,h1a,l1a,h8a,l8a,h9a,l9a;
            __half h0b,l0b,h1b,l1b,h8b,l8b,h9b,l9b;
            split_h(va[2*s],   h0a, l0a);  split_h(wa[2*s],   h1a, l1a);
            split_h(va[2*s+1], h8a, l8a);  split_h(wa[2*s+1], h9a, l9a);
            split_h(vb[2*s],   h0b, l0b);  split_h(wb[2*s],   h1b, l1b);
            split_h(vb[2*s+1], h8b, l8b);  split_h(wb[2*s+1], h9b, l9b);
            ah[s][0] = pack2(h0a, h1a);  ah[s][1] = pack2(h0b, h1b);
            ah[s][2] = pack2(h8a, h9a);  ah[s][3] = pack2(h8b, h9b);
            al[s][0] = pack2(l0a, l1a);  al[s][1] = pack2(l0b, l1b);
            al[s][2] = pack2(l8a, l9a);  al[s][3] = pack2(l8b, l9b);
        }

        float best0 = 3.402823e38f, best1 = 3.402823e38f;
        int   bidx0 = 0, bidx1 = 0;

        for (int tile = 0; tile < NTILES; ++tile) {
            cp_wait<0>();
            __syncthreads();
            if (tile + 1 < NTILES) {
                const u32  nbuf = sbase + ((tile + 1) & 1) * R_TILE;
                const char* src = (const char*)g_hl + (tile + 1) * (KTILE * 256);
#pragma unroll
                for (int i = 0; i < 8; ++i) {
                    int cell = t + 256 * i;
                    int nl = cell >> 4, r = cell & 15;
                    cp16(nbuf + nl * R_CSTRIDE + r * 16, src + cell * 16);
                }
                cp_commit();
            }
            const char* bufc = smem + (tile & 1) * R_TILE;
#pragma unroll 2
            for (int chunk = 0; chunk < 16; ++chunk) {
                const float4* bp = (const float4*)(bufc + (chunk * 8 + g) * R_CSTRIDE + tg * 16);
                float chh0=0.f,chh1=0.f,chh2=0.f,chh3=0.f;
                float chl0=0.f,chl1=0.f,chl2=0.f,chl3=0.f;
                float clh0=0.f,clh1=0.f,clh2=0.f,clh3=0.f;
#pragma unroll
                for (int s = 0; s < 4; ++s) {
                    float4 bv = bp[s * 4];
                    u32 bh0 = __float_as_uint(bv.x), bh1 = __float_as_uint(bv.y);
                    u32 bl0 = __float_as_uint(bv.z), bl1 = __float_as_uint(bv.w);
                    mma16816(chh0,chh1,chh2,chh3, ah[s][0],ah[s][1],ah[s][2],ah[s][3], bh0,bh1);
                    mma16816(chl0,chl1,chl2,chl3, ah[s][0],ah[s][1],ah[s][2],ah[s][3], bl0,bl1);
                    mma16816(clh0,clh1,clh2,clh3, al[s][0],al[s][1],al[s][2],al[s][3], bh0,bh1);
                }
                const int kg = tile * KTILE + chunk * 8 + 2 * tg;
                const float sq0 = ssq_s[kg], sq1 = ssq_s[kg + 1];
                float d00 = fmaf(NEG2LO, chl0 + clh0, fmaf(-2.f, chh0, sq0));
                float d01 = fmaf(NEG2LO, chl1 + clh1, fmaf(-2.f, chh1, sq1));
                float d10 = fmaf(NEG2LO, chl2 + clh2, fmaf(-2.f, chh2, sq0));
                float d11 = fmaf(NEG2LO, chl3 + clh3, fmaf(-2.f, chh3, sq1));
                if (d00 < best0) { best0 = d00; bidx0 = kg; }
                if (d01 < best0) { best0 = d01; bidx0 = kg + 1; }
                if (d10 < best1) { best1 = d10; bidx1 = kg; }
                if (d11 < best1) { best1 = d11; bidx1 = kg + 1; }
            }
        }

#pragma unroll
        for (int mask = 1; mask < 4; mask <<= 1) {
            float e0 = __shfl_xor_sync(0xffffffffu, best0, mask, 4);
            int   j0 = __shfl_xor_sync(0xffffffffu, bidx0, mask, 4);
            if (e0 < best0 || (e0 == best0 && j0 < bidx0)) { best0 = e0; bidx0 = j0; }
            float e1 = __shfl_xor_sync(0xffffffffu, best1, mask, 4);
            int   j1 = __shfl_xor_sync(0xffffffffu, bidx1, mask, 4);
            if (e1 < best1 || (e1 == best1 && j1 < bidx1)) { best1 = e1; bidx1 = j1; }
        }
        if (tg == 0) {
            ridx[w * 16 + g]     = bidx0;
            ridx[w * 16 + 8 + g] = bidx1;
        }
        __syncthreads();

        for (int i = t; i < m * 64; i += NT) {
            int pl = i >> 6, d = i & 63;
            int n = sids[pl], b = n >> 12, rem = n & 4095;
            out[b * (D_ * HW_) + d * HW_ + rem] = __ldg(&emb[d * K_ + ridx[pl]]);
        }
        if (t < m && out_size >= RES_ELEMS + NPTS)
            out[RES_ELEMS + sids[t]] = (float)ridx[t];
        __syncthreads();
    }
}

extern "C" void kernel_launch(void* const* d_in, const int* in_sizes, int n_in,
                              void* d_out, int out_size)
{
    const float* x   = (const float*)d_in[0];
    const float* emb = (const float*)d_in[1];
    if (n_in >= 2 && in_sizes[0] == D_ * K_ && in_sizes[1] == RES_ELEMS) {
        x   = (const float*)d_in[1];
        emb = (const float*)d_in[0];
    }
    static int configured = 0;
    if (!configured) {
        cudaFuncSetAttribute(vq_screen, cudaFuncAttributeMaxDynamicSharedMemorySize, S_SMEM);
        cudaFuncSetAttribute(vq_rescue, cudaFuncAttributeMaxDynamicSharedMemorySize, R_SMEM);
        configured = 1;
    }
    zero_flags<<<1, 1>>>();
    prep_all<<<64, 256>>>(emb);
    vq_screen<<<NPTS / PT, NT, S_SMEM>>>(x, emb, (float*)d_out, out_size);
    vq_rescue<<<1024, NT, R_SMEM>>>(x, emb, (float*)d_out, out_size);
}